// round 12
// baseline (speedup 1.0000x reference)
#include <cuda_runtime.h>

// BranchRoute: score = sigmoid(x @ gate_w + gate_b); mask_i = score_i > 0.5
// out = concat(x*m0, x*m1, x*(m0+m1)), each [N, D] fp32.
// sigmoid(z) > 0.5 <=> z > 0, so only the dot-product sign matters.
//
// R12 = R11 (best: bench 85.2us, kernel 81.3us, DRAM 74.2%) with two
// issue-order trims:
//  - x row loads (DRAM, ~600cyc) issue BEFORE gate loads (L2, ~240cyc) so
//    the long-latency loads overlap the gate fetches in block startup.
//  - dot uses 2 independent accumulators per score (shorter dependent-FMA
//    chain once loads land).
// Ten+ rounds established: ~74% DRAM is the 1R:3W HBM mixed-stream ceiling;
// wins come only from shaving L1tex/issue overhead around it.

#define THREADS 256
#define DIM 4096

__global__ void __launch_bounds__(THREADS)
branch_route_kernel(const float* __restrict__ x,
                    const float* __restrict__ gw,   // [D, 2]
                    const float* __restrict__ gb,   // [2]
                    float* __restrict__ out,        // [3, N, D]
                    int N)
{
    const int t = threadIdx.x;
    const int row = blockIdx.x;

    // Issue the DRAM loads first: row chunk (coalesced float4).
    const float4* xr = (const float4*)(x + (size_t)row * DIM);
    float4 v[4];
#pragma unroll
    for (int c = 0; c < 4; c++) v[c] = xr[c * 256 + t];

    // Then the gate pairs: 8 x LDG.128 (L2-resident), latency hides under x.
    float4 wv[8];
    {
        const float4* gw4 = (const float4*)gw;   // 2 (col-pairs) per float4
#pragma unroll
        for (int c = 0; c < 4; c++) {
            const int q = (c * 1024 + t * 4) >> 1;   // float4 index
            wv[c * 2 + 0] = __ldg(&gw4[q + 0]);      // cols 4t+0, 4t+1
            wv[c * 2 + 1] = __ldg(&gw4[q + 1]);      // cols 4t+2, 4t+3
        }
    }

    // Partial dots, 2 independent accumulators per score.
    float s0a = 0.f, s0b = 0.f, s1a = 0.f, s1b = 0.f;
#pragma unroll
    for (int c = 0; c < 4; c++) {
        const float4 wa = wv[c * 2 + 0];
        const float4 wb = wv[c * 2 + 1];
        s0a = fmaf(v[c].x, wa.x, s0a);  s1a = fmaf(v[c].x, wa.y, s1a);
        s0b = fmaf(v[c].y, wa.z, s0b);  s1b = fmaf(v[c].y, wa.w, s1b);
        s0a = fmaf(v[c].z, wb.x, s0a);  s1a = fmaf(v[c].z, wb.y, s1a);
        s0b = fmaf(v[c].w, wb.z, s0b);  s1b = fmaf(v[c].w, wb.w, s1b);
    }
    float s0 = s0a + s0b;
    float s1 = s1a + s1b;

    // Warp butterfly reduce.
#pragma unroll
    for (int o = 16; o > 0; o >>= 1) {
        s0 += __shfl_xor_sync(0xffffffffu, s0, o);
        s1 += __shfl_xor_sync(0xffffffffu, s1, o);
    }

    __shared__ __align__(16) float2 red[8];
    if ((t & 31) == 0) red[t >> 5] = make_float2(s0, s1);
    __syncthreads();

    float d0 = gb[0], d1 = gb[1];
#pragma unroll
    for (int k = 0; k < 4; k++) {
        const float4 r = ((const float4*)red)[k];   // two partials per LDS.128
        d0 += r.x + r.z;
        d1 += r.y + r.w;
    }

    const float f0 = d0 > 0.f ? 1.f : 0.f;
    const float f1 = d1 > 0.f ? 1.f : 0.f;
    const float fc = f0 + f1;

    const size_t base = (size_t)row * (DIM / 4);
    float4* __restrict__ p0 = (float4*)out + base;
    float4* __restrict__ p1 = (float4*)out + (size_t)N * (DIM / 4) + base;
    float4* __restrict__ pc = (float4*)out + (size_t)2 * N * (DIM / 4) + base;

#pragma unroll
    for (int c = 0; c < 4; c++) {
        const int idx = c * 256 + t;
        float4 a, b, s;
        a.x = f0 * v[c].x; a.y = f0 * v[c].y; a.z = f0 * v[c].z; a.w = f0 * v[c].w;
        b.x = f1 * v[c].x; b.y = f1 * v[c].y; b.z = f1 * v[c].z; b.w = f1 * v[c].w;
        s.x = fc * v[c].x; s.y = fc * v[c].y; s.z = fc * v[c].z; s.w = fc * v[c].w;
        p0[idx] = a;
        p1[idx] = b;
        pc[idx] = s;
    }
}

extern "C" void kernel_launch(void* const* d_in, const int* in_sizes, int n_in,
                              void* d_out, int out_size)
{
    const float* x  = (const float*)d_in[0];
    const float* gw = (const float*)d_in[1];
    const float* gb = (const float*)d_in[2];
    float* out = (float*)d_out;

    const int N = in_sizes[0] / DIM;   // 8192

    // One row per block: best measured scheduling granularity.
    branch_route_kernel<<<N, THREADS>>>(x, gw, gb, out, N);
}